// round 5
// baseline (speedup 1.0000x reference)
#include <cuda_runtime.h>
#include <cstdint>

#define LMAX  8
#define NSH   81   // (LMAX+1)^2
#define NF    45   // (LMAX+1)(LMAX+2)/2
#define TILE  128
#define NWARP (TILE / 32)
#define CHUNK_BYTES (32 * NSH * 4)   // 10368 B per warp, %16 == 0

__global__ __launch_bounds__(TILE)
void sh_kernel(const float* __restrict__ xyz,
               const float* __restrict__ F,
               float* __restrict__ out,
               int n)
{
    // Per-warp staging: 32 points x 81 floats = 10368 B, base 16B-aligned.
    __shared__ __align__(16) float s_out[NWARP * 32 * NSH];
    __shared__ float s_F[NF];

    const int tid  = threadIdx.x;
    const int lane = tid & 31;
    const int warp = tid >> 5;

    if (tid < NF) s_F[tid] = F[tid];
    __syncthreads();

    const int base_pt    = blockIdx.x * TILE;
    const int chunk_base = base_pt + warp * 32;
    const int p          = chunk_base + lane;

    float x = 0.0f, y = 0.0f, z = 1.0f;
    if (p < n) {
        x = xyz[3 * p + 0];
        y = xyz[3 * p + 1];
        z = xyz[3 * p + 2];
    }
    const float rinv = rsqrtf(x * x + y * y + z * z);
    x *= rinv; y *= rinv; z *= rinv;

    // Associated-Legendre recurrence (flattened triangular), fully unrolled.
    float Q[NF];
    Q[0] = 1.0f;
    #pragma unroll
    for (int l = 1; l <= LMAX; ++l) {
        const int b   = l * (l + 1) / 2;
        const int bp  = (l - 1) * l / 2;
        const int bpp = (l - 2) * (l - 1) / 2;   // unused when l==1
        Q[b + l]     = -(2.0f * l - 1.0f) * Q[bp + (l - 1)];
        Q[b + l - 1] = -z * Q[b + l];
        #pragma unroll
        for (int m = 0; m <= l - 2; ++m) {
            Q[b + m] = ((2.0f * l - 1.0f) * z * Q[bp + m]
                        - (float)(l + m - 1) * Q[bpp + m])
                       * (1.0f / (float)(l - m));
        }
    }
    // Fold normalization in once: Q[i] <- F[i]*Q[i].
    #pragma unroll
    for (int i = 0; i < NF; ++i) Q[i] *= s_F[i];

    float sv[LMAX + 1], cv[LMAX + 1];
    sv[0] = 0.0f; cv[0] = 1.0f;
    #pragma unroll
    for (int m = 1; m <= LMAX; ++m) {
        sv[m] = x * sv[m - 1] + y * cv[m - 1];
        cv[m] = x * cv[m - 1] - y * sv[m - 1];
    }

    const float inv_sqrt2 = 0.70710678118654752440f;
    float* const warp_buf = s_out + warp * (32 * NSH);

    if (p < n) {
        // stride 81 words: bank = (17*lane + c) mod 32 is a lane permutation
        // at fixed column c (17 odd) -> conflict-free STS.
        float* row = warp_buf + lane * NSH;
        #pragma unroll
        for (int l = 0; l <= LMAX; ++l) {
            const int b  = l * (l + 1) / 2;
            const int cb = l * l;
            #pragma unroll
            for (int k = l; k >= 1; --k)          // m = -l .. -1
                row[cb + l - k] = Q[b + k] * sv[k];
            row[cb + l] = Q[b] * inv_sqrt2;       // m = 0
            #pragma unroll
            for (int m = 1; m <= l; ++m)          // m = 1 .. l
                row[cb + l + m] = Q[b + m] * cv[m];
        }
    }
    __syncwarp();

    const int valid = min(32, n - chunk_base);

    if (valid == 32) {
        if (lane == 0) {
            asm volatile("fence.proxy.async.shared::cta;" ::: "memory");
            uint32_t src = (uint32_t)__cvta_generic_to_shared(warp_buf);
            float* dst   = out + (long long)chunk_base * NSH;
            asm volatile(
                "cp.async.bulk.global.shared::cta.bulk_group [%0], [%1], %2;"
                :: "l"(dst), "r"(src), "n"(CHUNK_BYTES) : "memory");
            asm volatile("cp.async.bulk.commit_group;" ::: "memory");
            // Only need the SMEM *read* side done before this CTA's smem dies;
            // do NOT wait for global visibility (that's the R3/R4 tail cost).
            asm volatile("cp.async.bulk.wait_group.read 0;" ::: "memory");
        }
    } else if (valid > 0) {
        // Tail path: scalar coalesced copy-out.
        const int total = valid * NSH;
        float* dst = out + (long long)chunk_base * NSH;
        for (int i = lane; i < total; i += 32)
            dst[i] = warp_buf[i];
    }
}

extern "C" void kernel_launch(void* const* d_in, const int* in_sizes, int n_in,
                              void* d_out, int out_size)
{
    const float* xyz = (const float*)d_in[0];
    const float* F   = (const float*)d_in[1];
    float* out       = (float*)d_out;
    const int n = in_sizes[0] / 3;
    const int grid = (n + TILE - 1) / TILE;
    sh_kernel<<<grid, TILE>>>(xyz, F, out, n);
}

// round 6
// speedup vs baseline: 1.1626x; 1.1626x over previous
#include <cuda_runtime.h>
#include <cstdint>

#define LMAX  8
#define NSH   81   // (LMAX+1)^2
#define NF    45   // (LMAX+1)(LMAX+2)/2
#define TILE  128
#define NWARP (TILE / 32)
#define CHUNK_BYTES (32 * NSH * 4)   // 10368 B per warp; %128 == 0 (full lines)

__global__ __launch_bounds__(TILE)
void sh_kernel(const float* __restrict__ xyz,
               const float* __restrict__ F,
               float* __restrict__ out,
               int n)
{
    // Per-warp staging: 32 points x 81 floats = 10368 B, base 16B-aligned.
    __shared__ __align__(16) float s_out[NWARP * 32 * NSH];
    __shared__ float s_F[NF];

    const int tid  = threadIdx.x;
    const int lane = tid & 31;
    const int warp = tid >> 5;

    if (tid < NF) s_F[tid] = F[tid];
    __syncthreads();

    const int base_pt    = blockIdx.x * TILE;
    const int chunk_base = base_pt + warp * 32;
    const int p          = chunk_base + lane;

    float x = 0.0f, y = 0.0f, z = 1.0f;
    if (p < n) {
        x = xyz[3 * p + 0];
        y = xyz[3 * p + 1];
        z = xyz[3 * p + 2];
    }
    const float rinv = rsqrtf(x * x + y * y + z * z);
    x *= rinv; y *= rinv; z *= rinv;

    // Associated-Legendre recurrence (flattened triangular), fully unrolled
    // -> constant indices -> registers. (No F-fold: R5 showed it costs +31 regs.)
    float Q[NF];
    Q[0] = 1.0f;
    #pragma unroll
    for (int l = 1; l <= LMAX; ++l) {
        const int b   = l * (l + 1) / 2;
        const int bp  = (l - 1) * l / 2;
        const int bpp = (l - 2) * (l - 1) / 2;   // unused when l==1
        Q[b + l]     = -(2.0f * l - 1.0f) * Q[bp + (l - 1)];
        Q[b + l - 1] = -z * Q[b + l];
        #pragma unroll
        for (int m = 0; m <= l - 2; ++m) {
            Q[b + m] = ((2.0f * l - 1.0f) * z * Q[bp + m]
                        - (float)(l + m - 1) * Q[bpp + m])
                       * (1.0f / (float)(l - m));
        }
    }

    float sv[LMAX + 1], cv[LMAX + 1];
    sv[0] = 0.0f; cv[0] = 1.0f;
    #pragma unroll
    for (int m = 1; m <= LMAX; ++m) {
        sv[m] = x * sv[m - 1] + y * cv[m - 1];
        cv[m] = x * cv[m - 1] - y * sv[m - 1];
    }

    const float inv_sqrt2 = 0.70710678118654752440f;
    float* const warp_buf = s_out + warp * (32 * NSH);

    if (p < n) {
        // stride 81 words: bank = (17*lane + c) mod 32 is a lane permutation
        // at fixed column c (17 odd) -> conflict-free STS.
        float* row = warp_buf + lane * NSH;
        #pragma unroll
        for (int l = 0; l <= LMAX; ++l) {
            const int b  = l * (l + 1) / 2;
            const int cb = l * l;
            #pragma unroll
            for (int k = l; k >= 1; --k)              // m = -l .. -1
                row[cb + l - k] = s_F[b + k] * Q[b + k] * sv[k];
            row[cb + l] = s_F[b] * Q[b] * inv_sqrt2;  // m = 0
            #pragma unroll
            for (int m = 1; m <= l; ++m)              // m = 1 .. l
                row[cb + l + m] = s_F[b + m] * Q[b + m] * cv[m];
        }
    }
    __syncwarp();

    const int valid = min(32, n - chunk_base);

    if (valid == 32) {
        if (lane == 0) {
            asm volatile("fence.proxy.async.shared::cta;" ::: "memory");
            uint32_t src = (uint32_t)__cvta_generic_to_shared(warp_buf);
            float* dst   = out + (long long)chunk_base * NSH;
            // evict_first: output is write-once/never-re-read -> start L2
            // writeback eagerly, don't let ~126MB of dirty lines pile up and
            // burst into the next graph replay.
            asm volatile(
                "{\n\t"
                ".reg .b64 pol;\n\t"
                "createpolicy.fractional.L2::evict_first.b64 pol, 1.0;\n\t"
                "cp.async.bulk.global.shared::cta.bulk_group.L2::cache_hint"
                " [%0], [%1], %2, pol;\n\t"
                "}"
                :: "l"(dst), "r"(src), "n"(CHUNK_BYTES) : "memory");
            asm volatile("cp.async.bulk.commit_group;" ::: "memory");
            // Full drain at CTA end (R3 config — benched best).
            asm volatile("cp.async.bulk.wait_group 0;" ::: "memory");
        }
    } else if (valid > 0) {
        // Tail path: scalar coalesced copy-out.
        const int total = valid * NSH;
        float* dst = out + (long long)chunk_base * NSH;
        for (int i = lane; i < total; i += 32)
            dst[i] = warp_buf[i];
    }
}

extern "C" void kernel_launch(void* const* d_in, const int* in_sizes, int n_in,
                              void* d_out, int out_size)
{
    const float* xyz = (const float*)d_in[0];
    const float* F   = (const float*)d_in[1];
    float* out       = (float*)d_out;
    const int n = in_sizes[0] / 3;
    const int grid = (n + TILE - 1) / TILE;
    sh_kernel<<<grid, TILE>>>(xyz, F, out, n);
}